// round 1
// baseline (speedup 1.0000x reference)
#include <cuda_runtime.h>

#define D_MODEL 1024
#define SEQ     4096
#define NH      16
#define DH      64

// -------- device scratch (no allocations allowed) --------
__device__ float g_Q [SEQ * D_MODEL];
__device__ float g_K [SEQ * D_MODEL];
__device__ float g_V [SEQ * D_MODEL];
__device__ float g_Qt[D_MODEL * SEQ];
__device__ float g_Kt[D_MODEL * SEQ];
__device__ float g_A [SEQ * D_MODEL];

// ============================================================
// SGEMM: C[M,N] = A[M,K] * B[N,K]^T   (both row-major, K contiguous)
// 128x128 block tile, BK=8, 256 threads, 8x8 per thread.
// ============================================================
__global__ __launch_bounds__(256, 2)
void sgemm_nt(const float* __restrict__ A, const float* __restrict__ B,
              float* __restrict__ C, int M, int N, int K)
{
    __shared__ __align__(16) float As[8][132];
    __shared__ __align__(16) float Bs[8][132];

    const int tid = threadIdx.x;
    const int tx  = tid & 15;
    const int ty  = tid >> 4;
    const int bm  = blockIdx.y * 128;
    const int bn  = blockIdx.x * 128;

    const int lrow = tid >> 1;          // 0..127
    const int lcol = (tid & 1) << 2;    // 0 or 4

    const float* Ap = A + (size_t)(bm + lrow) * K + lcol;
    const float* Bp = B + (size_t)(bn + lrow) * K + lcol;

    float acc[8][8];
    #pragma unroll
    for (int i = 0; i < 8; i++)
        #pragma unroll
        for (int j = 0; j < 8; j++) acc[i][j] = 0.f;

    float4 av = *(const float4*)Ap;
    float4 bv = *(const float4*)Bp;

    for (int k0 = 0; k0 < K; k0 += 8) {
        __syncthreads();
        As[lcol + 0][lrow] = av.x; As[lcol + 1][lrow] = av.y;
        As[lcol + 2][lrow] = av.z; As[lcol + 3][lrow] = av.w;
        Bs[lcol + 0][lrow] = bv.x; Bs[lcol + 1][lrow] = bv.y;
        Bs[lcol + 2][lrow] = bv.z; Bs[lcol + 3][lrow] = bv.w;
        __syncthreads();

        if (k0 + 8 < K) {   // prefetch next K-slab (overlaps with compute)
            av = *(const float4*)(Ap + k0 + 8);
            bv = *(const float4*)(Bp + k0 + 8);
        }

        #pragma unroll
        for (int kk = 0; kk < 8; kk++) {
            float ar[8], br[8];
            float4 t;
            t = *(const float4*)&As[kk][ty * 8];     ar[0]=t.x; ar[1]=t.y; ar[2]=t.z; ar[3]=t.w;
            t = *(const float4*)&As[kk][ty * 8 + 4]; ar[4]=t.x; ar[5]=t.y; ar[6]=t.z; ar[7]=t.w;
            t = *(const float4*)&Bs[kk][tx * 8];     br[0]=t.x; br[1]=t.y; br[2]=t.z; br[3]=t.w;
            t = *(const float4*)&Bs[kk][tx * 8 + 4]; br[4]=t.x; br[5]=t.y; br[6]=t.z; br[7]=t.w;
            #pragma unroll
            for (int i = 0; i < 8; i++)
                #pragma unroll
                for (int j = 0; j < 8; j++)
                    acc[i][j] += ar[i] * br[j];
        }
    }

    #pragma unroll
    for (int i = 0; i < 8; i++) {
        float* Cp = C + (size_t)(bm + ty * 8 + i) * N + bn + tx * 8;
        *(float4*)(Cp)     = make_float4(acc[i][0], acc[i][1], acc[i][2], acc[i][3]);
        *(float4*)(Cp + 4) = make_float4(acc[i][4], acc[i][5], acc[i][6], acc[i][7]);
    }
}

// ============================================================
// Transpose: in [SEQ][D_MODEL] -> out [D_MODEL][SEQ]
// 32x32 tiles, 32x8 threads
// ============================================================
__global__ void transpose_kernel(const float* __restrict__ in, float* __restrict__ out)
{
    __shared__ float t[32][33];
    const int d0 = blockIdx.x * 32;
    const int s0 = blockIdx.y * 32;
    const int tx = threadIdx.x, ty = threadIdx.y;

    #pragma unroll
    for (int i = 0; i < 4; i++)
        t[ty + i * 8][tx] = in[(size_t)(s0 + ty + i * 8) * D_MODEL + d0 + tx];
    __syncthreads();
    #pragma unroll
    for (int i = 0; i < 4; i++)
        out[(size_t)(d0 + ty + i * 8) * SEQ + s0 + tx] = t[tx][ty + i * 8];
}

// ============================================================
// Flash attention (fp32, online softmax).
// Qt, Kt: [D_MODEL][SEQ] (d-major).  V: [SEQ][D_MODEL].  O: [SEQ][D_MODEL].
// Grid: (SEQ/64, NH), 256 threads. Each CTA: 64 queries of one head.
// smem: sQ[d][r] 16K, sK[d][c] 16K, sV[c][d] 16K, sP[r][c] 16K = 64KB.
// ============================================================
__global__ __launch_bounds__(256)
void attn_kernel(const float* __restrict__ Qt, const float* __restrict__ Kt,
                 const float* __restrict__ V, float* __restrict__ O)
{
    extern __shared__ __align__(16) float smem[];
    float* sQ = smem;
    float* sK = sQ + 64 * 64;
    float* sV = sK + 64 * 64;
    float* sP = sV + 64 * 64;

    const int tid = threadIdx.x;
    const int tx  = tid & 15;   // key-tile / dh column group
    const int ty  = tid >> 4;   // query row group
    const int h   = blockIdx.y;
    const int q0  = blockIdx.x * 64;

    const int lr  = tid >> 4;          // load row 0..15 (stride 16)
    const int lc4 = (tid & 15) * 4;    // load col*4

    // load Q tile (d-major): sQ[d*64 + r]
    #pragma unroll
    for (int d = lr; d < 64; d += 16) {
        *(float4*)&sQ[d * 64 + lc4] =
            *(const float4*)(Qt + (size_t)(h * DH + d) * SEQ + q0 + lc4);
    }

    float m[4], l[4], o[4][4];
    #pragma unroll
    for (int i = 0; i < 4; i++) {
        m[i] = -1e30f; l[i] = 0.f;
        #pragma unroll
        for (int j = 0; j < 4; j++) o[i][j] = 0.f;
    }

    for (int kb = 0; kb < SEQ / 64; kb++) {
        const int k0 = kb * 64;
        __syncthreads();   // previous iteration done with sK/sV/sP
        #pragma unroll
        for (int d = lr; d < 64; d += 16) {
            *(float4*)&sK[d * 64 + lc4] =
                *(const float4*)(Kt + (size_t)(h * DH + d) * SEQ + k0 + lc4);
        }
        #pragma unroll
        for (int c = lr; c < 64; c += 16) {
            *(float4*)&sV[c * 64 + lc4] =
                *(const float4*)(V + (size_t)(k0 + c) * D_MODEL + h * DH + lc4);
        }
        __syncthreads();

        // S = Q K^T (outer product over d)
        float s[4][4];
        #pragma unroll
        for (int i = 0; i < 4; i++)
            #pragma unroll
            for (int j = 0; j < 4; j++) s[i][j] = 0.f;

        #pragma unroll 8
        for (int d = 0; d < 64; d++) {
            float qr[4], kr[4];
            float4 t;
            t = *(const float4*)&sQ[d * 64 + ty * 4]; qr[0]=t.x; qr[1]=t.y; qr[2]=t.z; qr[3]=t.w;
            t = *(const float4*)&sK[d * 64 + tx * 4]; kr[0]=t.x; kr[1]=t.y; kr[2]=t.z; kr[3]=t.w;
            #pragma unroll
            for (int i = 0; i < 4; i++)
                #pragma unroll
                for (int j = 0; j < 4; j++)
                    s[i][j] += qr[i] * kr[j];
        }

        // online softmax per query row (row spread across 16 lanes = half warp)
        #pragma unroll
        for (int i = 0; i < 4; i++) {
            float rm = -1e30f;
            #pragma unroll
            for (int j = 0; j < 4; j++) {
                s[i][j] *= 0.125f;            // 1/sqrt(64)
                rm = fmaxf(rm, s[i][j]);
            }
            #pragma unroll
            for (int w = 1; w < 16; w <<= 1)
                rm = fmaxf(rm, __shfl_xor_sync(0xffffffffu, rm, w));
            const float mn   = fmaxf(m[i], rm);
            const float corr = __expf(m[i] - mn);
            float rs = 0.f;
            #pragma unroll
            for (int j = 0; j < 4; j++) {
                s[i][j] = __expf(s[i][j] - mn);
                rs += s[i][j];
            }
            #pragma unroll
            for (int w = 1; w < 16; w <<= 1)
                rs += __shfl_xor_sync(0xffffffffu, rs, w);
            l[i] = l[i] * corr + rs;
            m[i] = mn;
            #pragma unroll
            for (int j = 0; j < 4; j++) o[i][j] *= corr;
        }

        // publish P tile
        #pragma unroll
        for (int i = 0; i < 4; i++)
            *(float4*)&sP[(ty * 4 + i) * 64 + tx * 4] =
                make_float4(s[i][0], s[i][1], s[i][2], s[i][3]);
        __syncthreads();

        // O += P * V
        #pragma unroll 4
        for (int c = 0; c < 64; c++) {
            float vr[4];
            float4 t = *(const float4*)&sV[c * 64 + tx * 4];
            vr[0] = t.x; vr[1] = t.y; vr[2] = t.z; vr[3] = t.w;
            #pragma unroll
            for (int i = 0; i < 4; i++) {
                const float p = sP[(ty * 4 + i) * 64 + c];
                #pragma unroll
                for (int j = 0; j < 4; j++)
                    o[i][j] += p * vr[j];
            }
        }
    }

    // epilogue: normalize + store
    #pragma unroll
    for (int i = 0; i < 4; i++) {
        const float inv = 1.f / l[i];
        *(float4*)(O + (size_t)(q0 + ty * 4 + i) * D_MODEL + h * DH + tx * 4) =
            make_float4(o[i][0] * inv, o[i][1] * inv, o[i][2] * inv, o[i][3] * inv);
    }
}

// ============================================================
extern "C" void kernel_launch(void* const* d_in, const int* in_sizes, int n_in,
                              void* d_out, int out_size)
{
    const float* x  = (const float*)d_in[0];
    const float* wq = (const float*)d_in[1];
    const float* wk = (const float*)d_in[2];
    const float* wv = (const float*)d_in[3];
    const float* wo = (const float*)d_in[4];
    float* out = (float*)d_out;

    float *pQ, *pK, *pV, *pQt, *pKt, *pA;
    cudaGetSymbolAddress((void**)&pQ,  g_Q);
    cudaGetSymbolAddress((void**)&pK,  g_K);
    cudaGetSymbolAddress((void**)&pV,  g_V);
    cudaGetSymbolAddress((void**)&pQt, g_Qt);
    cudaGetSymbolAddress((void**)&pKt, g_Kt);
    cudaGetSymbolAddress((void**)&pA,  g_A);

    const dim3 gg(D_MODEL / 128, SEQ / 128);   // (8, 32)
    sgemm_nt<<<gg, 256>>>(x, wq, pQ, SEQ, D_MODEL, D_MODEL);
    sgemm_nt<<<gg, 256>>>(x, wk, pK, SEQ, D_MODEL, D_MODEL);
    sgemm_nt<<<gg, 256>>>(x, wv, pV, SEQ, D_MODEL, D_MODEL);

    const dim3 tg(D_MODEL / 32, SEQ / 32);     // (32, 128)
    const dim3 tb(32, 8);
    transpose_kernel<<<tg, tb>>>(pQ, pQt);
    transpose_kernel<<<tg, tb>>>(pK, pKt);

    cudaFuncSetAttribute(attn_kernel,
                         cudaFuncAttributeMaxDynamicSharedMemorySize, 64 * 1024);
    attn_kernel<<<dim3(SEQ / 64, NH), 256, 64 * 1024>>>(pQt, pKt, pV, pA);

    sgemm_nt<<<gg, 256>>>(pA, wo, out, SEQ, D_MODEL, D_MODEL);
}

// round 14
// speedup vs baseline: 2.7043x; 2.7043x over previous
#include <cuda_runtime.h>
#include <cstdint>

#define D_MODEL 1024
#define SEQ     4096
#define NH      16
#define DH      64

// -------- device scratch (no allocations allowed) --------
__device__ float g_Q [SEQ * D_MODEL];
__device__ float g_K [SEQ * D_MODEL];
__device__ float g_V [SEQ * D_MODEL];
__device__ float g_Vt[D_MODEL * SEQ];
__device__ float g_A [SEQ * D_MODEL];

// ============================================================
// tf32 helpers (mma.sync -- supported on generic compute_103)
// ============================================================
__device__ __forceinline__ uint32_t f2tf32(float f) {
    uint32_t r;
    asm("cvt.rna.tf32.f32 %0, %1;" : "=r"(r) : "f"(f));
    return r;
}

// m16n8k8 row.col tf32: A frag 4 regs, B frag 2 regs, C frag 4 floats.
// A: a0=(g,c) a1=(g+8,c) a2=(g,c+4) a3=(g+8,c+4)   [g=lane>>2, c=lane&3]
// B: b0=(k=c,n=g) b1=(k=c+4,n=g)
// C: c0=(g,2c) c1=(g,2c+1) c2=(g+8,2c) c3=(g+8,2c+1)
__device__ __forceinline__ void mma_tf32(float* c, const uint32_t* a, const uint32_t* b) {
    asm volatile(
        "mma.sync.aligned.m16n8k8.row.col.f32.tf32.tf32.f32 "
        "{%0,%1,%2,%3}, {%4,%5,%6,%7}, {%8,%9}, {%0,%1,%2,%3};"
        : "+f"(c[0]), "+f"(c[1]), "+f"(c[2]), "+f"(c[3])
        : "r"(a[0]), "r"(a[1]), "r"(a[2]), "r"(a[3]),
          "r"(b[0]), "r"(b[1]));
}

// ============================================================
// tf32 mma GEMM: C[M,N] = A[M,K] * B[N,K]^T  (fp32 in/out)
// CTA 128x128, 256 thr (8 warps, 4x2), BK=32, smem stride 36 words.
// ============================================================
#define GS 36
#define GEMM_SMEM_BYTES (2 * 128 * GS * 4)   // 36864

__global__ __launch_bounds__(256)
void tf32_gemm(const float* __restrict__ A, const float* __restrict__ B,
               float* __restrict__ C, int M, int N, int K)
{
    extern __shared__ uint32_t smw[];
    uint32_t* sA = smw;              // [128][GS]
    uint32_t* sB = smw + 128 * GS;   // [128][GS]

    const int tid  = threadIdx.x;
    const int wid  = tid >> 5;
    const int lane = tid & 31;
    const int g    = lane >> 2;
    const int ct   = lane & 3;
    const int wm   = (wid & 3) * 32;     // warp M offset in tile
    const int wn   = (wid >> 2) * 64;    // warp N offset in tile
    const int bm   = blockIdx.y * 128;
    const int bn   = blockIdx.x * 128;

    float acc[2][8][4];
    #pragma unroll
    for (int mt = 0; mt < 2; mt++)
        #pragma unroll
        for (int nt = 0; nt < 8; nt++)
            #pragma unroll
            for (int j = 0; j < 4; j++) acc[mt][nt][j] = 0.f;

    const int nslab = K >> 5;
    for (int s = 0; s < nslab; s++) {
        __syncthreads();   // previous slab's frag reads done
        #pragma unroll
        for (int i = 0; i < 4; i++) {
            const int idx = tid + i * 256;     // 0..1023
            const int row = idx >> 3;          // 0..127
            const int c4  = (idx & 7) << 2;    // 0..28
            float4 va = *(const float4*)(A + (size_t)(bm + row) * K + s * 32 + c4);
            float4 vb = *(const float4*)(B + (size_t)(bn + row) * K + s * 32 + c4);
            uint32_t* pa = &sA[row * GS + c4];
            uint32_t* pb = &sB[row * GS + c4];
            pa[0] = f2tf32(va.x); pa[1] = f2tf32(va.y);
            pa[2] = f2tf32(va.z); pa[3] = f2tf32(va.w);
            pb[0] = f2tf32(vb.x); pb[1] = f2tf32(vb.y);
            pb[2] = f2tf32(vb.z); pb[3] = f2tf32(vb.w);
        }
        __syncthreads();

        #pragma unroll
        for (int ks = 0; ks < 4; ks++) {
            uint32_t af[2][4], bf[8][2];
            #pragma unroll
            for (int mt = 0; mt < 2; mt++) {
                const int r0 = wm + mt * 16 + g;
                af[mt][0] = sA[r0 * GS + ks * 8 + ct];
                af[mt][1] = sA[(r0 + 8) * GS + ks * 8 + ct];
                af[mt][2] = sA[r0 * GS + ks * 8 + ct + 4];
                af[mt][3] = sA[(r0 + 8) * GS + ks * 8 + ct + 4];
            }
            #pragma unroll
            for (int nt = 0; nt < 8; nt++) {
                const int n0 = wn + nt * 8 + g;
                bf[nt][0] = sB[n0 * GS + ks * 8 + ct];
                bf[nt][1] = sB[n0 * GS + ks * 8 + ct + 4];
            }
            #pragma unroll
            for (int mt = 0; mt < 2; mt++)
                #pragma unroll
                for (int nt = 0; nt < 8; nt++)
                    mma_tf32(acc[mt][nt], af[mt], bf[nt]);
        }
    }

    // epilogue
    #pragma unroll
    for (int mt = 0; mt < 2; mt++) {
        const int r0 = bm + wm + mt * 16 + g;
        #pragma unroll
        for (int nt = 0; nt < 8; nt++) {
            const int c0 = bn + wn + nt * 8 + 2 * ct;
            *(float2*)(C + (size_t)r0 * N + c0) =
                make_float2(acc[mt][nt][0], acc[mt][nt][1]);
            *(float2*)(C + (size_t)(r0 + 8) * N + c0) =
                make_float2(acc[mt][nt][2], acc[mt][nt][3]);
        }
    }
}

// ============================================================
// Transpose: in [SEQ][D_MODEL] -> out [D_MODEL][SEQ]
// ============================================================
__global__ void transpose_kernel(const float* __restrict__ in, float* __restrict__ out)
{
    __shared__ float t[32][33];
    const int d0 = blockIdx.x * 32;
    const int s0 = blockIdx.y * 32;
    const int tx = threadIdx.x, ty = threadIdx.y;

    #pragma unroll
    for (int i = 0; i < 4; i++)
        t[ty + i * 8][tx] = in[(size_t)(s0 + ty + i * 8) * D_MODEL + d0 + tx];
    __syncthreads();
    #pragma unroll
    for (int i = 0; i < 4; i++)
        out[(size_t)(d0 + ty + i * 8) * SEQ + s0 + tx] = t[tx][ty + i * 8];
}

// ============================================================
// mma.sync tf32 flash attention.
// CTA: 128 queries x 1 head, 256 thr (8 warps). Warp w owns query rows
// 16w..16w+15 and ALL 64 keys of each block -> softmax rows live in one
// quad (shfl xor 1,2 only). Q frags preloaded to regs. P is warp-private
// in smem (only __syncwarp before PV). O accumulated in C-fragments.
// smem (uint32 words, stride 68): K[64][68] + Vt[64][68] (overlaid by
// Q[128][68] during preload), P[128][68].
// ============================================================
#define AS 68
#define ATT_SMEM_BYTES (2 * 128 * AS * 4)   // 69632

__global__ __launch_bounds__(256)
void attn_mma(const float* __restrict__ Qg, const float* __restrict__ Kg,
              const float* __restrict__ Vtg, float* __restrict__ Og)
{
    extern __shared__ uint32_t smw[];
    uint32_t* sK = smw;              // [64][AS]
    uint32_t* sV = smw + 64 * AS;    // [64][AS]
    uint32_t* sQ = smw;              // [128][AS] overlays sK+sV (preload only)
    uint32_t* sP = smw + 128 * AS;   // [128][AS]

    const int tid  = threadIdx.x;
    const int wid  = tid >> 5;
    const int lane = tid & 31;
    const int g    = lane >> 2;
    const int ct   = lane & 3;
    const int wm   = wid * 16;       // warp's query-row base
    const int h    = blockIdx.y;
    const int q0   = blockIdx.x * 128;

    // ---- stage Q tile to smem, then extract frags to registers ----
    #pragma unroll
    for (int i = 0; i < 8; i++) {
        const int idx = tid + i * 256;     // 0..2047
        const int row = idx >> 4;          // 0..127
        const int c4  = (idx & 15) << 2;   // 0..60
        float4 v = *(const float4*)(Qg + (size_t)(q0 + row) * D_MODEL + h * DH + c4);
        uint32_t* p = &sQ[row * AS + c4];
        p[0] = f2tf32(v.x); p[1] = f2tf32(v.y);
        p[2] = f2tf32(v.z); p[3] = f2tf32(v.w);
    }
    __syncthreads();

    uint32_t qf[8][4];
    #pragma unroll
    for (int kd = 0; kd < 8; kd++) {
        const int r0 = wm + g;
        qf[kd][0] = sQ[r0 * AS + kd * 8 + ct];
        qf[kd][1] = sQ[(r0 + 8) * AS + kd * 8 + ct];
        qf[kd][2] = sQ[r0 * AS + kd * 8 + ct + 4];
        qf[kd][3] = sQ[(r0 + 8) * AS + kd * 8 + ct + 4];
    }

    float o[8][4];
    #pragma unroll
    for (int nt = 0; nt < 8; nt++)
        #pragma unroll
        for (int j = 0; j < 4; j++) o[nt][j] = 0.f;
    float m0 = -1e30f, m1 = -1e30f, l0 = 0.f, l1 = 0.f;

    for (int kb = 0; kb < SEQ / 64; kb++) {
        __syncthreads();   // Q-frag reads (kb=0) / prev PV sV reads done
        // ---- load K and Vt tiles ----
        #pragma unroll
        for (int i = 0; i < 4; i++) {
            const int idx = tid + i * 256;     // 0..1023
            const int row = idx >> 4;          // 0..63
            const int c4  = (idx & 15) << 2;   // 0..60
            float4 vk = *(const float4*)(Kg + (size_t)(kb * 64 + row) * D_MODEL + h * DH + c4);
            float4 vv = *(const float4*)(Vtg + (size_t)(h * DH + row) * SEQ + kb * 64 + c4);
            uint32_t* pk = &sK[row * AS + c4];
            uint32_t* pv = &sV[row * AS + c4];
            pk[0] = f2tf32(vk.x); pk[1] = f2tf32(vk.y);
            pk[2] = f2tf32(vk.z); pk[3] = f2tf32(vk.w);
            pv[0] = f2tf32(vv.x); pv[1] = f2tf32(vv.y);
            pv[2] = f2tf32(vv.z); pv[3] = f2tf32(vv.w);
        }
        __syncthreads();

        // ---- S = Q K^T : 8 n-tiles (keys), 8 k-steps (dh) ----
        float s[8][4];
        #pragma unroll
        for (int nt = 0; nt < 8; nt++)
            #pragma unroll
            for (int j = 0; j < 4; j++) s[nt][j] = 0.f;

        #pragma unroll
        for (int kd = 0; kd < 8; kd++) {
            #pragma unroll
            for (int nt = 0; nt < 8; nt++) {
                uint32_t bf[2];
                const int n0 = nt * 8 + g;
                bf[0] = sK[n0 * AS + kd * 8 + ct];
                bf[1] = sK[n0 * AS + kd * 8 + ct + 4];
                mma_tf32(s[nt], qf[kd], bf);
            }
        }

        // ---- online softmax (rows wm+g and wm+g+8; quad shuffles) ----
        float mb0 = -1e30f, mb1 = -1e30f;
        #pragma unroll
        for (int nt = 0; nt < 8; nt++) {
            s[nt][0] *= 0.125f; s[nt][1] *= 0.125f;
            s[nt][2] *= 0.125f; s[nt][3] *= 0.125f;
            mb0 = fmaxf(mb0, fmaxf(s[nt][0], s[nt][1]));
            mb1 = fmaxf(mb1, fmaxf(s[nt][2], s[nt][3]));
        }
        mb0 = fmaxf(mb0, __shfl_xor_sync(0xffffffffu, mb0, 1));
        mb0 = fmaxf(mb0, __shfl_xor_sync(0xffffffffu, mb0, 2));
        mb1 = fmaxf(mb1, __shfl_xor_sync(0xffffffffu, mb1, 1));
        mb1 = fmaxf(mb1, __shfl_xor_sync(0xffffffffu, mb1, 2));

        const float mn0 = fmaxf(m0, mb0);
        const float mn1 = fmaxf(m1, mb1);
        const float corr0 = __expf(m0 - mn0);
        const float corr1 = __expf(m1 - mn1);
        m0 = mn0; m1 = mn1;

        float rs0 = 0.f, rs1 = 0.f;
        #pragma unroll
        for (int nt = 0; nt < 8; nt++) {
            s[nt][0] = __expf(s[nt][0] - mn0);
            s[nt][1] = __expf(s[nt][1] - mn0);
            s[nt][2] = __expf(s[nt][2] - mn1);
            s[nt][3] = __expf(s[nt][3] - mn1);
            rs0 += s[nt][0] + s[nt][1];
            rs1 += s[nt][2] + s[nt][3];
        }
        rs0 += __shfl_xor_sync(0xffffffffu, rs0, 1);
        rs0 += __shfl_xor_sync(0xffffffffu, rs0, 2);
        rs1 += __shfl_xor_sync(0xffffffffu, rs1, 1);
        rs1 += __shfl_xor_sync(0xffffffffu, rs1, 2);
        l0 = l0 * corr0 + rs0;
        l1 = l1 * corr1 + rs1;

        // rescale O
        #pragma unroll
        for (int nt = 0; nt < 8; nt++) {
            o[nt][0] *= corr0; o[nt][1] *= corr0;
            o[nt][2] *= corr1; o[nt][3] *= corr1;
        }

        // ---- store P (warp-private rows) ----
        #pragma unroll
        for (int nt = 0; nt < 8; nt++) {
            const int r0 = wm + g;
            sP[r0 * AS + nt * 8 + 2 * ct]           = f2tf32(s[nt][0]);
            sP[r0 * AS + nt * 8 + 2 * ct + 1]       = f2tf32(s[nt][1]);
            sP[(r0 + 8) * AS + nt * 8 + 2 * ct]     = f2tf32(s[nt][2]);
            sP[(r0 + 8) * AS + nt * 8 + 2 * ct + 1] = f2tf32(s[nt][3]);
        }
        __syncwarp();

        // ---- O += P V : 8 n-tiles (dh), 8 k-steps (keys) ----
        #pragma unroll
        for (int kk = 0; kk < 8; kk++) {
            uint32_t af[4];
            const int r0 = wm + g;
            af[0] = sP[r0 * AS + kk * 8 + ct];
            af[1] = sP[(r0 + 8) * AS + kk * 8 + ct];
            af[2] = sP[r0 * AS + kk * 8 + ct + 4];
            af[3] = sP[(r0 + 8) * AS + kk * 8 + ct + 4];
            #pragma unroll
            for (int nt = 0; nt < 8; nt++) {
                uint32_t bf[2];
                const int n0 = nt * 8 + g;
                bf[0] = sV[n0 * AS + kk * 8 + ct];
                bf[1] = sV[n0 * AS + kk * 8 + ct + 4];
                mma_tf32(o[nt], af, bf);
            }
        }
    }

    // ---- epilogue ----
    const float inv0 = 1.f / l0;
    const float inv1 = 1.f / l1;
    const int r0 = q0 + wm + g;
    #pragma unroll
    for (int nt = 0; nt < 8; nt++) {
        const int c0 = h * DH + nt * 8 + 2 * ct;
        *(float2*)(Og + (size_t)r0 * D_MODEL + c0) =
            make_float2(o[nt][0] * inv0, o[nt][1] * inv0);
        *(float2*)(Og + (size_t)(r0 + 8) * D_MODEL + c0) =
            make_float2(o[nt][2] * inv1, o[nt][3] * inv1);
    }
}

// ============================================================
extern "C" void kernel_launch(void* const* d_in, const int* in_sizes, int n_in,
                              void* d_out, int out_size)
{
    const float* x  = (const float*)d_in[0];
    const float* wq = (const float*)d_in[1];
    const float* wk = (const float*)d_in[2];
    const float* wv = (const float*)d_in[3];
    const float* wo = (const float*)d_in[4];
    float* out = (float*)d_out;

    float *pQ, *pK, *pV, *pVt, *pA;
    cudaGetSymbolAddress((void**)&pQ,  g_Q);
    cudaGetSymbolAddress((void**)&pK,  g_K);
    cudaGetSymbolAddress((void**)&pV,  g_V);
    cudaGetSymbolAddress((void**)&pVt, g_Vt);
    cudaGetSymbolAddress((void**)&pA,  g_A);

    cudaFuncSetAttribute(tf32_gemm,
                         cudaFuncAttributeMaxDynamicSharedMemorySize, GEMM_SMEM_BYTES);
    cudaFuncSetAttribute(attn_mma,
                         cudaFuncAttributeMaxDynamicSharedMemorySize, ATT_SMEM_BYTES);

    const dim3 gg(D_MODEL / 128, SEQ / 128);   // (8, 32)
    tf32_gemm<<<gg, 256, GEMM_SMEM_BYTES>>>(x, wq, pQ, SEQ, D_MODEL, D_MODEL);
    tf32_gemm<<<gg, 256, GEMM_SMEM_BYTES>>>(x, wk, pK, SEQ, D_MODEL, D_MODEL);
    tf32_gemm<<<gg, 256, GEMM_SMEM_BYTES>>>(x, wv, pV, SEQ, D_MODEL, D_MODEL);

    const dim3 tg(D_MODEL / 32, SEQ / 32);     // (32, 128)
    const dim3 tb(32, 8);
    transpose_kernel<<<tg, tb>>>(pV, pVt);

    attn_mma<<<dim3(SEQ / 128, NH), 256, ATT_SMEM_BYTES>>>(pQ, pK, pVt, pA);

    tf32_gemm<<<gg, 256, GEMM_SMEM_BYTES>>>(pA, wo, out, SEQ, D_MODEL, D_MODEL);
}

// round 15
// speedup vs baseline: 2.7592x; 1.0203x over previous
#include <cuda_runtime.h>
#include <cstdint>

#define D_MODEL 1024
#define SEQ     4096
#define NH      16
#define DH      64

// -------- device scratch (no allocations allowed) --------
__device__ float g_Q [SEQ * D_MODEL];
__device__ float g_K [SEQ * D_MODEL];
__device__ float g_V [SEQ * D_MODEL];
__device__ float g_Vt[D_MODEL * SEQ];
__device__ float g_A [SEQ * D_MODEL];

// ============================================================
// tf32 helpers (mma.sync -- supported on generic compute_103)
// ============================================================
__device__ __forceinline__ uint32_t f2tf32(float f) {
    uint32_t r;
    asm("cvt.rna.tf32.f32 %0, %1;" : "=r"(r) : "f"(f));
    return r;
}

// m16n8k8 row.col tf32: A frag 4 regs, B frag 2 regs, C frag 4 floats.
__device__ __forceinline__ void mma_tf32(float* c, const uint32_t* a, const uint32_t* b) {
    asm volatile(
        "mma.sync.aligned.m16n8k8.row.col.f32.tf32.tf32.f32 "
        "{%0,%1,%2,%3}, {%4,%5,%6,%7}, {%8,%9}, {%0,%1,%2,%3};"
        : "+f"(c[0]), "+f"(c[1]), "+f"(c[2]), "+f"(c[3])
        : "r"(a[0]), "r"(a[1]), "r"(a[2]), "r"(a[3]),
          "r"(b[0]), "r"(b[1]));
}

// ============================================================
// tf32 mma GEMM: C[M,N] = A[M,K] * B[N,K]^T  (fp32 in/out)
// CTA 128x128, 256 thr (8 warps, 4x2), BK=32, stride 36 words.
// Double-buffered smem + register prefetch: ONE sync per slab.
// ============================================================
#define GS 36
#define GEMM_BUF (2 * 128 * GS)                  // words per buffer (A+B)
#define GEMM_SMEM_BYTES (2 * GEMM_BUF * 4)       // 73728

__global__ __launch_bounds__(256)
void tf32_gemm(const float* __restrict__ A, const float* __restrict__ B,
               float* __restrict__ C, int M, int N, int K)
{
    extern __shared__ uint32_t smw[];

    const int tid  = threadIdx.x;
    const int wid  = tid >> 5;
    const int lane = tid & 31;
    const int g    = lane >> 2;
    const int ct   = lane & 3;
    const int wm   = (wid & 3) * 32;
    const int wn   = (wid >> 2) * 64;
    const int bm   = blockIdx.y * 128;
    const int bn   = blockIdx.x * 128;

    // per-thread load coords (4 chunks of 256 threads covering 128x8 float4)
    const int lrow[1] = {0};
    (void)lrow;

    float acc[2][8][4];
    #pragma unroll
    for (int mt = 0; mt < 2; mt++)
        #pragma unroll
        for (int nt = 0; nt < 8; nt++)
            #pragma unroll
            for (int j = 0; j < 4; j++) acc[mt][nt][j] = 0.f;

    const int nslab = K >> 5;

    float4 pva[4], pvb[4];
    // ---- preload slab 0 ----
    #pragma unroll
    for (int i = 0; i < 4; i++) {
        const int idx = tid + i * 256;
        const int row = idx >> 3;
        const int c4  = (idx & 7) << 2;
        pva[i] = *(const float4*)(A + (size_t)(bm + row) * K + c4);
        pvb[i] = *(const float4*)(B + (size_t)(bn + row) * K + c4);
    }
    {
        uint32_t* sA = smw;
        uint32_t* sB = smw + 128 * GS;
        #pragma unroll
        for (int i = 0; i < 4; i++) {
            const int idx = tid + i * 256;
            const int row = idx >> 3;
            const int c4  = (idx & 7) << 2;
            uint32_t* pa = &sA[row * GS + c4];
            uint32_t* pb = &sB[row * GS + c4];
            pa[0] = f2tf32(pva[i].x); pa[1] = f2tf32(pva[i].y);
            pa[2] = f2tf32(pva[i].z); pa[3] = f2tf32(pva[i].w);
            pb[0] = f2tf32(pvb[i].x); pb[1] = f2tf32(pvb[i].y);
            pb[2] = f2tf32(pvb[i].z); pb[3] = f2tf32(pvb[i].w);
        }
    }
    __syncthreads();

    for (int s = 0; s < nslab; s++) {
        const uint32_t* sA = smw + (s & 1) * GEMM_BUF;
        const uint32_t* sB = sA + 128 * GS;

        // prefetch next slab's globals into registers
        if (s + 1 < nslab) {
            const int k0 = (s + 1) << 5;
            #pragma unroll
            for (int i = 0; i < 4; i++) {
                const int idx = tid + i * 256;
                const int row = idx >> 3;
                const int c4  = (idx & 7) << 2;
                pva[i] = *(const float4*)(A + (size_t)(bm + row) * K + k0 + c4);
                pvb[i] = *(const float4*)(B + (size_t)(bn + row) * K + k0 + c4);
            }
        }

        // compute on current buffer
        #pragma unroll
        for (int ks = 0; ks < 4; ks++) {
            uint32_t af[2][4], bf[8][2];
            #pragma unroll
            for (int mt = 0; mt < 2; mt++) {
                const int r0 = wm + mt * 16 + g;
                af[mt][0] = sA[r0 * GS + ks * 8 + ct];
                af[mt][1] = sA[(r0 + 8) * GS + ks * 8 + ct];
                af[mt][2] = sA[r0 * GS + ks * 8 + ct + 4];
                af[mt][3] = sA[(r0 + 8) * GS + ks * 8 + ct + 4];
            }
            #pragma unroll
            for (int nt = 0; nt < 8; nt++) {
                const int n0 = wn + nt * 8 + g;
                bf[nt][0] = sB[n0 * GS + ks * 8 + ct];
                bf[nt][1] = sB[n0 * GS + ks * 8 + ct + 4];
            }
            #pragma unroll
            for (int mt = 0; mt < 2; mt++)
                #pragma unroll
                for (int nt = 0; nt < 8; nt++)
                    mma_tf32(acc[mt][nt], af[mt], bf[nt]);
        }

        // store next slab into alternate buffer, then single sync
        if (s + 1 < nslab) {
            uint32_t* dA = smw + ((s + 1) & 1) * GEMM_BUF;
            uint32_t* dB = dA + 128 * GS;
            #pragma unroll
            for (int i = 0; i < 4; i++) {
                const int idx = tid + i * 256;
                const int row = idx >> 3;
                const int c4  = (idx & 7) << 2;
                uint32_t* pa = &dA[row * GS + c4];
                uint32_t* pb = &dB[row * GS + c4];
                pa[0] = f2tf32(pva[i].x); pa[1] = f2tf32(pva[i].y);
                pa[2] = f2tf32(pva[i].z); pa[3] = f2tf32(pva[i].w);
                pb[0] = f2tf32(pvb[i].x); pb[1] = f2tf32(pvb[i].y);
                pb[2] = f2tf32(pvb[i].z); pb[3] = f2tf32(pvb[i].w);
            }
            __syncthreads();
        }
    }

    // epilogue
    #pragma unroll
    for (int mt = 0; mt < 2; mt++) {
        const int r0 = bm + wm + mt * 16 + g;
        #pragma unroll
        for (int nt = 0; nt < 8; nt++) {
            const int c0 = bn + wn + nt * 8 + 2 * ct;
            *(float2*)(C + (size_t)r0 * N + c0) =
                make_float2(acc[mt][nt][0], acc[mt][nt][1]);
            *(float2*)(C + (size_t)(r0 + 8) * N + c0) =
                make_float2(acc[mt][nt][2], acc[mt][nt][3]);
        }
    }
}

// ============================================================
// Transpose: in [SEQ][D_MODEL] -> out [D_MODEL][SEQ]
// ============================================================
__global__ void transpose_kernel(const float* __restrict__ in, float* __restrict__ out)
{
    __shared__ float t[32][33];
    const int d0 = blockIdx.x * 32;
    const int s0 = blockIdx.y * 32;
    const int tx = threadIdx.x, ty = threadIdx.y;

    #pragma unroll
    for (int i = 0; i < 4; i++)
        t[ty + i * 8][tx] = in[(size_t)(s0 + ty + i * 8) * D_MODEL + d0 + tx];
    __syncthreads();
    #pragma unroll
    for (int i = 0; i < 4; i++)
        out[(size_t)(d0 + ty + i * 8) * SEQ + s0 + tx] = t[tx][ty + i * 8];
}

// ============================================================
// mma.sync tf32 flash attention, double-buffered K/V.
// CTA: 128 queries x 1 head, 256 thr (8 warps). Warp owns 16 query rows.
// Q pre-scaled by 1/8 (exact). ONE __syncthreads per key-block.
// smem: 2 x (K[64][AS] + V[64][AS]) + P[128][AS] = 104448 B.
// ============================================================
#define AS 68
#define KVBUF (2 * 64 * AS)                       // words per K+V buffer
#define ATT_SMEM_BYTES ((2 * KVBUF + 128 * AS) * 4)   // 104448

__global__ __launch_bounds__(256)
void attn_mma(const float* __restrict__ Qg, const float* __restrict__ Kg,
              const float* __restrict__ Vtg, float* __restrict__ Og)
{
    extern __shared__ uint32_t smw[];
    uint32_t* sP = smw + 2 * KVBUF;   // [128][AS]

    const int tid  = threadIdx.x;
    const int wid  = tid >> 5;
    const int lane = tid & 31;
    const int g    = lane >> 2;
    const int ct   = lane & 3;
    const int wm   = wid * 16;
    const int h    = blockIdx.y;
    const int q0   = blockIdx.x * 128;

    // ---- stage Q (pre-scaled by 0.125) into smem base, extract frags ----
    {
        uint32_t* sQ = smw;   // [128][AS], overlays KV buffer 0
        #pragma unroll
        for (int i = 0; i < 8; i++) {
            const int idx = tid + i * 256;
            const int row = idx >> 4;
            const int c4  = (idx & 15) << 2;
            float4 v = *(const float4*)(Qg + (size_t)(q0 + row) * D_MODEL + h * DH + c4);
            uint32_t* p = &sQ[row * AS + c4];
            p[0] = f2tf32(v.x * 0.125f); p[1] = f2tf32(v.y * 0.125f);
            p[2] = f2tf32(v.z * 0.125f); p[3] = f2tf32(v.w * 0.125f);
        }
    }
    __syncthreads();

    uint32_t qf[8][4];
    {
        const uint32_t* sQ = smw;
        #pragma unroll
        for (int kd = 0; kd < 8; kd++) {
            const int r0 = wm + g;
            qf[kd][0] = sQ[r0 * AS + kd * 8 + ct];
            qf[kd][1] = sQ[(r0 + 8) * AS + kd * 8 + ct];
            qf[kd][2] = sQ[r0 * AS + kd * 8 + ct + 4];
            qf[kd][3] = sQ[(r0 + 8) * AS + kd * 8 + ct + 4];
        }
    }
    __syncthreads();   // all Q reads done before buffer 0 is overwritten

    // ---- load tile 0 into buffer 0 ----
    float4 pvk[4], pvv[4];
    #pragma unroll
    for (int i = 0; i < 4; i++) {
        const int idx = tid + i * 256;
        const int row = idx >> 4;
        const int c4  = (idx & 15) << 2;
        pvk[i] = *(const float4*)(Kg + (size_t)row * D_MODEL + h * DH + c4);
        pvv[i] = *(const float4*)(Vtg + (size_t)(h * DH + row) * SEQ + c4);
    }
    {
        uint32_t* dK = smw;
        uint32_t* dV = smw + 64 * AS;
        #pragma unroll
        for (int i = 0; i < 4; i++) {
            const int idx = tid + i * 256;
            const int row = idx >> 4;
            const int c4  = (idx & 15) << 2;
            uint32_t* pk = &dK[row * AS + c4];
            uint32_t* pv = &dV[row * AS + c4];
            pk[0] = f2tf32(pvk[i].x); pk[1] = f2tf32(pvk[i].y);
            pk[2] = f2tf32(pvk[i].z); pk[3] = f2tf32(pvk[i].w);
            pv[0] = f2tf32(pvv[i].x); pv[1] = f2tf32(pvv[i].y);
            pv[2] = f2tf32(pvv[i].z); pv[3] = f2tf32(pvv[i].w);
        }
    }
    __syncthreads();

    float o[8][4];
    #pragma unroll
    for (int nt = 0; nt < 8; nt++)
        #pragma unroll
        for (int j = 0; j < 4; j++) o[nt][j] = 0.f;
    float m0 = -1e30f, m1 = -1e30f, l0 = 0.f, l1 = 0.f;

    for (int kb = 0; kb < SEQ / 64; kb++) {
        const uint32_t* sK = smw + (kb & 1) * KVBUF;
        const uint32_t* sV = sK + 64 * AS;

        // prefetch next tile's globals
        if (kb + 1 < SEQ / 64) {
            const int k0 = (kb + 1) * 64;
            #pragma unroll
            for (int i = 0; i < 4; i++) {
                const int idx = tid + i * 256;
                const int row = idx >> 4;
                const int c4  = (idx & 15) << 2;
                pvk[i] = *(const float4*)(Kg + (size_t)(k0 + row) * D_MODEL + h * DH + c4);
                pvv[i] = *(const float4*)(Vtg + (size_t)(h * DH + row) * SEQ + k0 + c4);
            }
        }

        // ---- S = (Q/8) K^T ----
        float s[8][4];
        #pragma unroll
        for (int nt = 0; nt < 8; nt++)
            #pragma unroll
            for (int j = 0; j < 4; j++) s[nt][j] = 0.f;

        #pragma unroll
        for (int kd = 0; kd < 8; kd++) {
            #pragma unroll
            for (int nt = 0; nt < 8; nt++) {
                uint32_t bf[2];
                const int n0 = nt * 8 + g;
                bf[0] = sK[n0 * AS + kd * 8 + ct];
                bf[1] = sK[n0 * AS + kd * 8 + ct + 4];
                mma_tf32(s[nt], qf[kd], bf);
            }
        }

        // ---- online softmax (quad shuffles) ----
        float mb0 = -1e30f, mb1 = -1e30f;
        #pragma unroll
        for (int nt = 0; nt < 8; nt++) {
            mb0 = fmaxf(mb0, fmaxf(s[nt][0], s[nt][1]));
            mb1 = fmaxf(mb1, fmaxf(s[nt][2], s[nt][3]));
        }
        mb0 = fmaxf(mb0, __shfl_xor_sync(0xffffffffu, mb0, 1));
        mb0 = fmaxf(mb0, __shfl_xor_sync(0xffffffffu, mb0, 2));
        mb1 = fmaxf(mb1, __shfl_xor_sync(0xffffffffu, mb1, 1));
        mb1 = fmaxf(mb1, __shfl_xor_sync(0xffffffffu, mb1, 2));

        const float mn0 = fmaxf(m0, mb0);
        const float mn1 = fmaxf(m1, mb1);
        const float corr0 = __expf(m0 - mn0);
        const float corr1 = __expf(m1 - mn1);
        m0 = mn0; m1 = mn1;

        float rs0 = 0.f, rs1 = 0.f;
        #pragma unroll
        for (int nt = 0; nt < 8; nt++) {
            s[nt][0] = __expf(s[nt][0] - mn0);
            s[nt][1] = __expf(s[nt][1] - mn0);
            s[nt][2] = __expf(s[nt][2] - mn1);
            s[nt][3] = __expf(s[nt][3] - mn1);
            rs0 += s[nt][0] + s[nt][1];
            rs1 += s[nt][2] + s[nt][3];
        }
        rs0 += __shfl_xor_sync(0xffffffffu, rs0, 1);
        rs0 += __shfl_xor_sync(0xffffffffu, rs0, 2);
        rs1 += __shfl_xor_sync(0xffffffffu, rs1, 1);
        rs1 += __shfl_xor_sync(0xffffffffu, rs1, 2);
        l0 = l0 * corr0 + rs0;
        l1 = l1 * corr1 + rs1;

        #pragma unroll
        for (int nt = 0; nt < 8; nt++) {
            o[nt][0] *= corr0; o[nt][1] *= corr0;
            o[nt][2] *= corr1; o[nt][3] *= corr1;
        }

        // ---- store P (warp-private rows) ----
        #pragma unroll
        for (int nt = 0; nt < 8; nt++) {
            const int r0 = wm + g;
            sP[r0 * AS + nt * 8 + 2 * ct]           = f2tf32(s[nt][0]);
            sP[r0 * AS + nt * 8 + 2 * ct + 1]       = f2tf32(s[nt][1]);
            sP[(r0 + 8) * AS + nt * 8 + 2 * ct]     = f2tf32(s[nt][2]);
            sP[(r0 + 8) * AS + nt * 8 + 2 * ct + 1] = f2tf32(s[nt][3]);
        }
        __syncwarp();

        // ---- O += P V ----
        #pragma unroll
        for (int kk = 0; kk < 8; kk++) {
            uint32_t af[4];
            const int r0 = wm + g;
            af[0] = sP[r0 * AS + kk * 8 + ct];
            af[1] = sP[(r0 + 8) * AS + kk * 8 + ct];
            af[2] = sP[r0 * AS + kk * 8 + ct + 4];
            af[3] = sP[(r0 + 8) * AS + kk * 8 + ct + 4];
            #pragma unroll
            for (int nt = 0; nt < 8; nt++) {
                uint32_t bf[2];
                const int n0 = nt * 8 + g;
                bf[0] = sV[n0 * AS + kk * 8 + ct];
                bf[1] = sV[n0 * AS + kk * 8 + ct + 4];
                mma_tf32(o[nt], af, bf);
            }
        }

        // ---- store prefetched tile into alternate buffer, single sync ----
        if (kb + 1 < SEQ / 64) {
            uint32_t* dK = smw + ((kb + 1) & 1) * KVBUF;
            uint32_t* dV = dK + 64 * AS;
            #pragma unroll
            for (int i = 0; i < 4; i++) {
                const int idx = tid + i * 256;
                const int row = idx >> 4;
                const int c4  = (idx & 15) << 2;
                uint32_t* pk = &dK[row * AS + c4];
                uint32_t* pv = &dV[row * AS + c4];
                pk[0] = f2tf32(pvk[i].x); pk[1] = f2tf32(pvk[i].y);
                pk[2] = f2tf32(pvk[i].z); pk[3] = f2tf32(pvk[i].w);
                pv[0] = f2tf32(pvv[i].x); pv[1] = f2tf32(pvv[i].y);
                pv[2] = f2tf32(pvv[i].z); pv[3] = f2tf32(pvv[i].w);
            }
            __syncthreads();
        }
    }

    // ---- epilogue ----
    const float inv0 = 1.f / l0;
    const float inv1 = 1.f / l1;
    const int r0 = q0 + wm + g;
    #pragma unroll
    for (int nt = 0; nt < 8; nt++) {
        const int c0 = h * DH + nt * 8 + 2 * ct;
        *(float2*)(Og + (size_t)r0 * D_MODEL + c0) =
            make_float2(o[nt][0] * inv0, o[nt][1] * inv0);
        *(float2*)(Og + (size_t)(r0 + 8) * D_MODEL + c0) =
            make_float2(o[nt][2] * inv1, o[nt][3] * inv1);
    }
}

// ============================================================
extern "C" void kernel_launch(void* const* d_in, const int* in_sizes, int n_in,
                              void* d_out, int out_size)
{
    const float* x  = (const float*)d_in[0];
    const float* wq = (const float*)d_in[1];
    const float* wk = (const float*)d_in[2];
    const float* wv = (const float*)d_in[3];
    const float* wo = (const float*)d_in[4];
    float* out = (float*)d_out;

    float *pQ, *pK, *pV, *pVt, *pA;
    cudaGetSymbolAddress((void**)&pQ,  g_Q);
    cudaGetSymbolAddress((void**)&pK,  g_K);
    cudaGetSymbolAddress((void**)&pV,  g_V);
    cudaGetSymbolAddress((void**)&pVt, g_Vt);
    cudaGetSymbolAddress((void**)&pA,  g_A);

    cudaFuncSetAttribute(tf32_gemm,
                         cudaFuncAttributeMaxDynamicSharedMemorySize, GEMM_SMEM_BYTES);
    cudaFuncSetAttribute(attn_mma,
                         cudaFuncAttributeMaxDynamicSharedMemorySize, ATT_SMEM_BYTES);

    const dim3 gg(D_MODEL / 128, SEQ / 128);   // (8, 32)
    tf32_gemm<<<gg, 256, GEMM_SMEM_BYTES>>>(x, wq, pQ, SEQ, D_MODEL, D_MODEL);
    tf32_gemm<<<gg, 256, GEMM_SMEM_BYTES>>>(x, wk, pK, SEQ, D_MODEL, D_MODEL);
    tf32_gemm<<<gg, 256, GEMM_SMEM_BYTES>>>(x, wv, pV, SEQ, D_MODEL, D_MODEL);

    const dim3 tg(D_MODEL / 32, SEQ / 32);     // (32, 128)
    const dim3 tb(32, 8);
    transpose_kernel<<<tg, tb>>>(pV, pVt);

    attn_mma<<<dim3(SEQ / 128, NH), 256, ATT_SMEM_BYTES>>>(pQ, pK, pVt, pA);

    tf32_gemm<<<gg, 256, GEMM_SMEM_BYTES>>>(pA, wo, out, SEQ, D_MODEL, D_MODEL);
}

// round 17
// speedup vs baseline: 2.8970x; 1.0499x over previous
#include <cuda_runtime.h>
#include <cstdint>

#define D_MODEL 1024
#define SEQ     4096
#define NH      16
#define DH      64

// -------- device scratch (no allocations allowed) --------
__device__ float g_Q [SEQ * D_MODEL];
__device__ float g_K [SEQ * D_MODEL];
__device__ float g_V [SEQ * D_MODEL];
__device__ float g_Vt[D_MODEL * SEQ];
__device__ float g_A [SEQ * D_MODEL];

// ============================================================
// tf32 helpers (mma.sync -- supported on generic compute_103)
// ============================================================
__device__ __forceinline__ uint32_t f2tf32(float f) {
    uint32_t r;
    asm("cvt.rna.tf32.f32 %0, %1;" : "=r"(r) : "f"(f));
    return r;
}

__device__ __forceinline__ void mma_tf32(float* c, const uint32_t* a, const uint32_t* b) {
    asm volatile(
        "mma.sync.aligned.m16n8k8.row.col.f32.tf32.tf32.f32 "
        "{%0,%1,%2,%3}, {%4,%5,%6,%7}, {%8,%9}, {%0,%1,%2,%3};"
        : "+f"(c[0]), "+f"(c[1]), "+f"(c[2]), "+f"(c[3])
        : "r"(a[0]), "r"(a[1]), "r"(a[2]), "r"(a[3]),
          "r"(b[0]), "r"(b[1]));
}

// ============================================================
// tf32 mma GEMM (unchanged measured-good version)
// ============================================================
#define GS 36
#define GEMM_BUF (2 * 128 * GS)
#define GEMM_SMEM_BYTES (2 * GEMM_BUF * 4)   // 73728

__global__ __launch_bounds__(256)
void tf32_gemm(const float* __restrict__ A, const float* __restrict__ B,
               float* __restrict__ C, int M, int N, int K)
{
    extern __shared__ uint32_t smw[];

    const int tid  = threadIdx.x;
    const int wid  = tid >> 5;
    const int lane = tid & 31;
    const int g    = lane >> 2;
    const int ct   = lane & 3;
    const int wm   = (wid & 3) * 32;
    const int wn   = (wid >> 2) * 64;
    const int bm   = blockIdx.y * 128;
    const int bn   = blockIdx.x * 128;

    float acc[2][8][4];
    #pragma unroll
    for (int mt = 0; mt < 2; mt++)
        #pragma unroll
        for (int nt = 0; nt < 8; nt++)
            #pragma unroll
            for (int j = 0; j < 4; j++) acc[mt][nt][j] = 0.f;

    const int nslab = K >> 5;

    float4 pva[4], pvb[4];
    #pragma unroll
    for (int i = 0; i < 4; i++) {
        const int idx = tid + i * 256;
        const int row = idx >> 3;
        const int c4  = (idx & 7) << 2;
        pva[i] = *(const float4*)(A + (size_t)(bm + row) * K + c4);
        pvb[i] = *(const float4*)(B + (size_t)(bn + row) * K + c4);
    }
    {
        uint32_t* sA = smw;
        uint32_t* sB = smw + 128 * GS;
        #pragma unroll
        for (int i = 0; i < 4; i++) {
            const int idx = tid + i * 256;
            const int row = idx >> 3;
            const int c4  = (idx & 7) << 2;
            uint32_t* pa = &sA[row * GS + c4];
            uint32_t* pb = &sB[row * GS + c4];
            pa[0] = f2tf32(pva[i].x); pa[1] = f2tf32(pva[i].y);
            pa[2] = f2tf32(pva[i].z); pa[3] = f2tf32(pva[i].w);
            pb[0] = f2tf32(pvb[i].x); pb[1] = f2tf32(pvb[i].y);
            pb[2] = f2tf32(pvb[i].z); pb[3] = f2tf32(pvb[i].w);
        }
    }
    __syncthreads();

    for (int s = 0; s < nslab; s++) {
        const uint32_t* sA = smw + (s & 1) * GEMM_BUF;
        const uint32_t* sB = sA + 128 * GS;

        if (s + 1 < nslab) {
            const int k0 = (s + 1) << 5;
            #pragma unroll
            for (int i = 0; i < 4; i++) {
                const int idx = tid + i * 256;
                const int row = idx >> 3;
                const int c4  = (idx & 7) << 2;
                pva[i] = *(const float4*)(A + (size_t)(bm + row) * K + k0 + c4);
                pvb[i] = *(const float4*)(B + (size_t)(bn + row) * K + k0 + c4);
            }
        }

        #pragma unroll
        for (int ks = 0; ks < 4; ks++) {
            uint32_t af[2][4], bf[8][2];
            #pragma unroll
            for (int mt = 0; mt < 2; mt++) {
                const int r0 = wm + mt * 16 + g;
                af[mt][0] = sA[r0 * GS + ks * 8 + ct];
                af[mt][1] = sA[(r0 + 8) * GS + ks * 8 + ct];
                af[mt][2] = sA[r0 * GS + ks * 8 + ct + 4];
                af[mt][3] = sA[(r0 + 8) * GS + ks * 8 + ct + 4];
            }
            #pragma unroll
            for (int nt = 0; nt < 8; nt++) {
                const int n0 = wn + nt * 8 + g;
                bf[nt][0] = sB[n0 * GS + ks * 8 + ct];
                bf[nt][1] = sB[n0 * GS + ks * 8 + ct + 4];
            }
            #pragma unroll
            for (int mt = 0; mt < 2; mt++)
                #pragma unroll
                for (int nt = 0; nt < 8; nt++)
                    mma_tf32(acc[mt][nt], af[mt], bf[nt]);
        }

        if (s + 1 < nslab) {
            uint32_t* dA = smw + ((s + 1) & 1) * GEMM_BUF;
            uint32_t* dB = dA + 128 * GS;
            #pragma unroll
            for (int i = 0; i < 4; i++) {
                const int idx = tid + i * 256;
                const int row = idx >> 3;
                const int c4  = (idx & 7) << 2;
                uint32_t* pa = &dA[row * GS + c4];
                uint32_t* pb = &dB[row * GS + c4];
                pa[0] = f2tf32(pva[i].x); pa[1] = f2tf32(pva[i].y);
                pa[2] = f2tf32(pva[i].z); pa[3] = f2tf32(pva[i].w);
                pb[0] = f2tf32(pvb[i].x); pb[1] = f2tf32(pvb[i].y);
                pb[2] = f2tf32(pvb[i].z); pb[3] = f2tf32(pvb[i].w);
            }
            __syncthreads();
        }
    }

    #pragma unroll
    for (int mt = 0; mt < 2; mt++) {
        const int r0 = bm + wm + mt * 16 + g;
        #pragma unroll
        for (int nt = 0; nt < 8; nt++) {
            const int c0 = bn + wn + nt * 8 + 2 * ct;
            *(float2*)(C + (size_t)r0 * N + c0) =
                make_float2(acc[mt][nt][0], acc[mt][nt][1]);
            *(float2*)(C + (size_t)(r0 + 8) * N + c0) =
                make_float2(acc[mt][nt][2], acc[mt][nt][3]);
        }
    }
}

// ============================================================
// Transpose: in [SEQ][D_MODEL] -> out [D_MODEL][SEQ]
// ============================================================
__global__ void transpose_kernel(const float* __restrict__ in, float* __restrict__ out)
{
    __shared__ float t[32][33];
    const int d0 = blockIdx.x * 32;
    const int s0 = blockIdx.y * 32;
    const int tx = threadIdx.x, ty = threadIdx.y;

    #pragma unroll
    for (int i = 0; i < 4; i++)
        t[ty + i * 8][tx] = in[(size_t)(s0 + ty + i * 8) * D_MODEL + d0 + tx];
    __syncthreads();
    #pragma unroll
    for (int i = 0; i < 4; i++)
        out[(size_t)(d0 + ty + i * 8) * SEQ + s0 + tx] = t[tx][ty + i * 8];
}

// ============================================================
// mma.sync tf32 flash attention, KEY-SPLIT across warp pairs.
// Warp = (qg = wid&3, kh = wid>>2): query rows qg*32..+31, key half
// kh*32..+31 of each 64-key block. P buffers are PER-KEY-HALF
// (fix for R16 race: both halves previously shared one P region).
// smem: 2 KV buffers + 2 x P[128][36]; merge overlay reuses P space.
// ============================================================
#define AS 68
#define PS 36
#define KVBUF (2 * 64 * AS)                       // words per K+V buffer
#define SP_OFF (2 * KVBUF)                        // P base (2 x 128 x PS)
#define MB_STRIDE 66
#define ML_OFF (SP_OFF + 2 * 128 * PS)            // m,l merge array
#define ATT_SMEM_BYTES ((ML_OFF + 256) * 4)       // 107520

__global__ __launch_bounds__(256)
void attn_mma(const float* __restrict__ Qg, const float* __restrict__ Kg,
              const float* __restrict__ Vtg, float* __restrict__ Og)
{
    extern __shared__ uint32_t smw[];
    float* MB = (float*)(smw + SP_OFF);           // merge O overlay [128][66]
    float* ML = (float*)(smw + ML_OFF);           // merge m,l [128][2]

    const int tid  = threadIdx.x;
    const int wid  = tid >> 5;
    const int lane = tid & 31;
    const int g    = lane >> 2;
    const int ct   = lane & 3;
    const int qg   = wid & 3;
    const int kh   = wid >> 2;                    // key half 0/1
    const int wm   = qg * 32;                     // query-row base
    const int h    = blockIdx.y;
    const int q0   = blockIdx.x * 128;

    uint32_t* sP = smw + SP_OFF + kh * 128 * PS;  // per-key-half P region

    // ---- stage Q (pre-scaled by 0.125) into KV buffer 0 region ----
    {
        uint32_t* sQ = smw;
        #pragma unroll
        for (int i = 0; i < 8; i++) {
            const int idx = tid + i * 256;
            const int row = idx >> 4;
            const int c4  = (idx & 15) << 2;
            float4 v = *(const float4*)(Qg + (size_t)(q0 + row) * D_MODEL + h * DH + c4);
            uint32_t* p = &sQ[row * AS + c4];
            p[0] = f2tf32(v.x * 0.125f); p[1] = f2tf32(v.y * 0.125f);
            p[2] = f2tf32(v.z * 0.125f); p[3] = f2tf32(v.w * 0.125f);
        }
    }
    __syncthreads();

    uint32_t qf[8][2][4];
    {
        const uint32_t* sQ = smw;
        #pragma unroll
        for (int kd = 0; kd < 8; kd++)
            #pragma unroll
            for (int mt = 0; mt < 2; mt++) {
                const int r0 = wm + mt * 16 + g;
                qf[kd][mt][0] = sQ[r0 * AS + kd * 8 + ct];
                qf[kd][mt][1] = sQ[(r0 + 8) * AS + kd * 8 + ct];
                qf[kd][mt][2] = sQ[r0 * AS + kd * 8 + ct + 4];
                qf[kd][mt][3] = sQ[(r0 + 8) * AS + kd * 8 + ct + 4];
            }
    }
    __syncthreads();

    // ---- load tile 0 into buffer 0 ----
    float4 pvk[4], pvv[4];
    #pragma unroll
    for (int i = 0; i < 4; i++) {
        const int idx = tid + i * 256;
        const int row = idx >> 4;
        const int c4  = (idx & 15) << 2;
        pvk[i] = *(const float4*)(Kg + (size_t)row * D_MODEL + h * DH + c4);
        pvv[i] = *(const float4*)(Vtg + (size_t)(h * DH + row) * SEQ + c4);
    }
    {
        uint32_t* dK = smw;
        uint32_t* dV = smw + 64 * AS;
        #pragma unroll
        for (int i = 0; i < 4; i++) {
            const int idx = tid + i * 256;
            const int row = idx >> 4;
            const int c4  = (idx & 15) << 2;
            uint32_t* pk = &dK[row * AS + c4];
            uint32_t* pv = &dV[row * AS + c4];
            pk[0] = f2tf32(pvk[i].x); pk[1] = f2tf32(pvk[i].y);
            pk[2] = f2tf32(pvk[i].z); pk[3] = f2tf32(pvk[i].w);
            pv[0] = f2tf32(pvv[i].x); pv[1] = f2tf32(pvv[i].y);
            pv[2] = f2tf32(pvv[i].z); pv[3] = f2tf32(pvv[i].w);
        }
    }
    __syncthreads();

    float o[2][8][4];
    #pragma unroll
    for (int mt = 0; mt < 2; mt++)
        #pragma unroll
        for (int nt = 0; nt < 8; nt++)
            #pragma unroll
            for (int j = 0; j < 4; j++) o[mt][nt][j] = 0.f;
    float m[2][2] = {{-1e30f, -1e30f}, {-1e30f, -1e30f}};
    float l[2][2] = {{0.f, 0.f}, {0.f, 0.f}};

    for (int kb = 0; kb < SEQ / 64; kb++) {
        const uint32_t* sK = smw + (kb & 1) * KVBUF;
        const uint32_t* sV = sK + 64 * AS;

        if (kb + 1 < SEQ / 64) {
            const int k0 = (kb + 1) * 64;
            #pragma unroll
            for (int i = 0; i < 4; i++) {
                const int idx = tid + i * 256;
                const int row = idx >> 4;
                const int c4  = (idx & 15) << 2;
                pvk[i] = *(const float4*)(Kg + (size_t)(k0 + row) * D_MODEL + h * DH + c4);
                pvv[i] = *(const float4*)(Vtg + (size_t)(h * DH + row) * SEQ + k0 + c4);
            }
        }

        // ---- S = (Q/8) K^T over THIS warp's 32 keys (4 n-tiles) ----
        float s[2][4][4];
        #pragma unroll
        for (int mt = 0; mt < 2; mt++)
            #pragma unroll
            for (int nt = 0; nt < 4; nt++)
                #pragma unroll
                for (int j = 0; j < 4; j++) s[mt][nt][j] = 0.f;

        #pragma unroll
        for (int kd = 0; kd < 8; kd++) {
            #pragma unroll
            for (int nt = 0; nt < 4; nt++) {
                uint32_t bf[2];
                const int n0 = kh * 32 + nt * 8 + g;
                bf[0] = sK[n0 * AS + kd * 8 + ct];
                bf[1] = sK[n0 * AS + kd * 8 + ct + 4];
                #pragma unroll
                for (int mt = 0; mt < 2; mt++)
                    mma_tf32(s[mt][nt], qf[kd][mt], bf);
            }
        }

        // ---- online softmax per m-tile ----
        #pragma unroll
        for (int mt = 0; mt < 2; mt++) {
            float mb0 = -1e30f, mb1 = -1e30f;
            #pragma unroll
            for (int nt = 0; nt < 4; nt++) {
                mb0 = fmaxf(mb0, fmaxf(s[mt][nt][0], s[mt][nt][1]));
                mb1 = fmaxf(mb1, fmaxf(s[mt][nt][2], s[mt][nt][3]));
            }
            mb0 = fmaxf(mb0, __shfl_xor_sync(0xffffffffu, mb0, 1));
            mb0 = fmaxf(mb0, __shfl_xor_sync(0xffffffffu, mb0, 2));
            mb1 = fmaxf(mb1, __shfl_xor_sync(0xffffffffu, mb1, 1));
            mb1 = fmaxf(mb1, __shfl_xor_sync(0xffffffffu, mb1, 2));

            const float mn0 = fmaxf(m[mt][0], mb0);
            const float mn1 = fmaxf(m[mt][1], mb1);
            const float corr0 = __expf(m[mt][0] - mn0);
            const float corr1 = __expf(m[mt][1] - mn1);
            m[mt][0] = mn0; m[mt][1] = mn1;

            float rs0 = 0.f, rs1 = 0.f;
            #pragma unroll
            for (int nt = 0; nt < 4; nt++) {
                s[mt][nt][0] = __expf(s[mt][nt][0] - mn0);
                s[mt][nt][1] = __expf(s[mt][nt][1] - mn0);
                s[mt][nt][2] = __expf(s[mt][nt][2] - mn1);
                s[mt][nt][3] = __expf(s[mt][nt][3] - mn1);
                rs0 += s[mt][nt][0] + s[mt][nt][1];
                rs1 += s[mt][nt][2] + s[mt][nt][3];
            }
            rs0 += __shfl_xor_sync(0xffffffffu, rs0, 1);
            rs0 += __shfl_xor_sync(0xffffffffu, rs0, 2);
            rs1 += __shfl_xor_sync(0xffffffffu, rs1, 1);
            rs1 += __shfl_xor_sync(0xffffffffu, rs1, 2);
            l[mt][0] = l[mt][0] * corr0 + rs0;
            l[mt][1] = l[mt][1] * corr1 + rs1;

            #pragma unroll
            for (int nt = 0; nt < 8; nt++) {
                o[mt][nt][0] *= corr0; o[mt][nt][1] *= corr0;
                o[mt][nt][2] *= corr1; o[mt][nt][3] *= corr1;
            }

            // store P tile into THIS key-half's private region
            #pragma unroll
            for (int nt = 0; nt < 4; nt++) {
                const int r0 = wm + mt * 16 + g;
                sP[r0 * PS + nt * 8 + 2 * ct]           = f2tf32(s[mt][nt][0]);
                sP[r0 * PS + nt * 8 + 2 * ct + 1]       = f2tf32(s[mt][nt][1]);
                sP[(r0 + 8) * PS + nt * 8 + 2 * ct]     = f2tf32(s[mt][nt][2]);
                sP[(r0 + 8) * PS + nt * 8 + 2 * ct + 1] = f2tf32(s[mt][nt][3]);
            }
        }
        __syncwarp();

        // ---- O += P V over THIS warp's 32 keys (4 k-steps) ----
        #pragma unroll
        for (int kk = 0; kk < 4; kk++) {
            uint32_t af[2][4];
            #pragma unroll
            for (int mt = 0; mt < 2; mt++) {
                const int r0 = wm + mt * 16 + g;
                af[mt][0] = sP[r0 * PS + kk * 8 + ct];
                af[mt][1] = sP[(r0 + 8) * PS + kk * 8 + ct];
                af[mt][2] = sP[r0 * PS + kk * 8 + ct + 4];
                af[mt][3] = sP[(r0 + 8) * PS + kk * 8 + ct + 4];
            }
            #pragma unroll
            for (int nt = 0; nt < 8; nt++) {
                uint32_t bf[2];
                const int n0 = nt * 8 + g;
                const int kcol = kh * 32 + kk * 8 + ct;
                bf[0] = sV[n0 * AS + kcol];
                bf[1] = sV[n0 * AS + kcol + 4];
                #pragma unroll
                for (int mt = 0; mt < 2; mt++)
                    mma_tf32(o[mt][nt], af[mt], bf);
            }
        }

        // ---- store prefetched tile into alternate buffer ----
        if (kb + 1 < SEQ / 64) {
            uint32_t* dK = smw + ((kb + 1) & 1) * KVBUF;
            uint32_t* dV = dK + 64 * AS;
            #pragma unroll
            for (int i = 0; i < 4; i++) {
                const int idx = tid + i * 256;
                const int row = idx >> 4;
                const int c4  = (idx & 15) << 2;
                uint32_t* pk = &dK[row * AS + c4];
                uint32_t* pv = &dV[row * AS + c4];
                pk[0] = f2tf32(pvk[i].x); pk[1] = f2tf32(pvk[i].y);
                pk[2] = f2tf32(pvk[i].z); pk[3] = f2tf32(pvk[i].w);
                pv[0] = f2tf32(pvv[i].x); pv[1] = f2tf32(pvv[i].y);
                pv[2] = f2tf32(pvv[i].z); pv[3] = f2tf32(pvv[i].w);
            }
            __syncthreads();
        }
    }

    // ---- merge the two key halves ----
    __syncthreads();   // all PV reads of sP done before overlay write
    if (kh == 1) {
        #pragma unroll
        for (int mt = 0; mt < 2; mt++) {
            const int r0 = wm + mt * 16 + g;
            #pragma unroll
            for (int nt = 0; nt < 8; nt++) {
                MB[r0 * MB_STRIDE + nt * 8 + 2 * ct]           = o[mt][nt][0];
                MB[r0 * MB_STRIDE + nt * 8 + 2 * ct + 1]       = o[mt][nt][1];
                MB[(r0 + 8) * MB_STRIDE + nt * 8 + 2 * ct]     = o[mt][nt][2];
                MB[(r0 + 8) * MB_STRIDE + nt * 8 + 2 * ct + 1] = o[mt][nt][3];
            }
            if (ct == 0) {
                ML[r0 * 2]           = m[mt][0];
                ML[r0 * 2 + 1]       = l[mt][0];
                ML[(r0 + 8) * 2]     = m[mt][1];
                ML[(r0 + 8) * 2 + 1] = l[mt][1];
            }
        }
    }
    __syncthreads();
    if (kh == 0) {
        #pragma unroll
        for (int mt = 0; mt < 2; mt++) {
            const int r0 = wm + mt * 16 + g;
            const float m1a = ML[r0 * 2],       l1a = ML[r0 * 2 + 1];
            const float m1b = ML[(r0 + 8) * 2], l1b = ML[(r0 + 8) * 2 + 1];
            const float mma0 = fmaxf(m[mt][0], m1a);
            const float mma1 = fmaxf(m[mt][1], m1b);
            const float ca0 = __expf(m[mt][0] - mma0), cb0 = __expf(m1a - mma0);
            const float ca1 = __expf(m[mt][1] - mma1), cb1 = __expf(m1b - mma1);
            const float inv0 = 1.f / (l[mt][0] * ca0 + l1a * cb0);
            const float inv1 = 1.f / (l[mt][1] * ca1 + l1b * cb1);
            #pragma unroll
            for (int nt = 0; nt < 8; nt++) {
                const int c0 = h * DH + nt * 8 + 2 * ct;
                float v0 = (o[mt][nt][0] * ca0 + MB[r0 * MB_STRIDE + nt * 8 + 2 * ct]     * cb0) * inv0;
                float v1 = (o[mt][nt][1] * ca0 + MB[r0 * MB_STRIDE + nt * 8 + 2 * ct + 1] * cb0) * inv0;
                float v2 = (o[mt][nt][2] * ca1 + MB[(r0 + 8) * MB_STRIDE + nt * 8 + 2 * ct]     * cb1) * inv1;
                float v3 = (o[mt][nt][3] * ca1 + MB[(r0 + 8) * MB_STRIDE + nt * 8 + 2 * ct + 1] * cb1) * inv1;
                *(float2*)(Og + (size_t)(q0 + r0) * D_MODEL + c0)     = make_float2(v0, v1);
                *(float2*)(Og + (size_t)(q0 + r0 + 8) * D_MODEL + c0) = make_float2(v2, v3);
            }
        }
    }
}

// ============================================================
extern "C" void kernel_launch(void* const* d_in, const int* in_sizes, int n_in,
                              void* d_out, int out_size)
{
    const float* x  = (const float*)d_in[0];
    const float* wq = (const float*)d_in[1];
    const float* wk = (const float*)d_in[2];
    const float* wv = (const float*)d_in[3];
    const float* wo = (const float*)d_in[4];
    float* out = (float*)d_out;

    float *pQ, *pK, *pV, *pVt, *pA;
    cudaGetSymbolAddress((void**)&pQ,  g_Q);
    cudaGetSymbolAddress((void**)&pK,  g_K);
    cudaGetSymbolAddress((void**)&pV,  g_V);
    cudaGetSymbolAddress((void**)&pVt, g_Vt);
    cudaGetSymbolAddress((void**)&pA,  g_A);

    cudaFuncSetAttribute(tf32_gemm,
                         cudaFuncAttributeMaxDynamicSharedMemorySize, GEMM_SMEM_BYTES);
    cudaFuncSetAttribute(attn_mma,
                         cudaFuncAttributeMaxDynamicSharedMemorySize, ATT_SMEM_BYTES);

    const dim3 gg(D_MODEL / 128, SEQ / 128);   // (8, 32)
    tf32_gemm<<<gg, 256, GEMM_SMEM_BYTES>>>(x, wq, pQ, SEQ, D_MODEL, D_MODEL);
    tf32_gemm<<<gg, 256, GEMM_SMEM_BYTES>>>(x, wk, pK, SEQ, D_MODEL, D_MODEL);
    tf32_gemm<<<gg, 256, GEMM_SMEM_BYTES>>>(x, wv, pV, SEQ, D_MODEL, D_MODEL);

    const dim3 tg(D_MODEL / 32, SEQ / 32);     // (32, 128)
    const dim3 tb(32, 8);
    transpose_kernel<<<tg, tb>>>(pV, pVt);

    attn_mma<<<dim3(SEQ / 128, NH), 256, ATT_SMEM_BYTES>>>(pQ, pK, pVt, pA);

    tf32_gemm<<<gg, 256, GEMM_SMEM_BYTES>>>(pA, wo, out, SEQ, D_MODEL, D_MODEL);
}